// round 14
// baseline (speedup 1.0000x reference)
#include <cuda_runtime.h>
#include <cuda_bf16.h>
#include <cstdint>

// Problem constants
#define BATCH 64
#define CIN   64
#define H     128
#define W     128
#define COUT  256
#define OH    126
#define OW    126
#define MTOT  (OH*OW)     // 15876
#define KTOT  (CIN*9)     // 576
#define NSTG  9           // 9 stages of K=64 (one per (kh,kw))

#define XSCALE 6.0f       // x quant range (N(0,1): clip prob ~2e-9)

// Scratch (__device__ globals: allocation-free; zero-initialized pad)
// x quantized s8, NHWC: g_xq[b][h][w][ci]; +256B pad for edge-row overreads
__device__ __align__(16) int8_t g_xq[(size_t)BATCH*H*W*CIN + 256];
// weights quantized s8, K-reordered rows: g_wq[co][k'], k' = (kh*3+kw)*64 + ci
__device__ __align__(16) int8_t g_wq[COUT*KTOT];
// combined dequant scale per channel: sw[co] * (XSCALE/127)
__device__ float g_wsc[COUT];

// ---------------- prologue kernels ----------------

__device__ __forceinline__ int8_t q8(float v, float qs) {
    int q = __float2int_rn(v * qs);
    q = q > 127 ? 127 : (q < -127 ? -127 : q);
    return (int8_t)q;
}

__global__ void quant_x_kernel(const float* __restrict__ x) {
    // one block per (h, b): transpose [64c][128w] -> [w][c], quantize to s8
    __shared__ int8_t tile[64][132];
    const int h = blockIdx.x, b = blockIdx.y, tid = threadIdx.x;
    const float qs = 127.0f / XSCALE;
    #pragma unroll
    for (int i = 0; i < 8; i++) {
        int idx = tid + i * 256;            // 2048 float4 loads
        int c = idx >> 5, w4 = (idx & 31) * 4;
        float4 v = *reinterpret_cast<const float4*>(
            x + ((((size_t)b * CIN + c) * H + h) * W + w4));
        tile[c][w4 + 0] = q8(v.x, qs);
        tile[c][w4 + 1] = q8(v.y, qs);
        tile[c][w4 + 2] = q8(v.z, qs);
        tile[c][w4 + 3] = q8(v.w, qs);
    }
    __syncthreads();
    int8_t* dst = g_xq + ((size_t)(b * H + h) * W) * CIN;
    #pragma unroll
    for (int i = 0; i < 8; i++) {
        int idx = tid + i * 256;            // 2048 u32 stores
        int w = idx >> 4, c4 = (idx & 15) * 4;
        uint32_t v = ((uint32_t)(uint8_t)tile[c4 + 0][w])
                   | ((uint32_t)(uint8_t)tile[c4 + 1][w] << 8)
                   | ((uint32_t)(uint8_t)tile[c4 + 2][w] << 16)
                   | ((uint32_t)(uint8_t)tile[c4 + 3][w] << 24);
        *reinterpret_cast<uint32_t*>(dst + (size_t)w * CIN + c4) = v;
    }
}

__global__ void quant_w_kernel(const float* __restrict__ w, float* __restrict__ out) {
    // one block per co, 64 threads (one per ci); per-channel max quantization
    __shared__ float smax[2];
    const int co = blockIdx.x, t = threadIdx.x;
    float vals[9];
    float m = 0.0f;
    #pragma unroll
    for (int j = 0; j < 9; j++) {
        vals[j] = w[co * KTOT + t * 9 + j];   // OIHW: ci = t, khw = j
        m = fmaxf(m, fabsf(vals[j]));
    }
    #pragma unroll
    for (int off = 16; off >= 1; off >>= 1)
        m = fmaxf(m, __shfl_xor_sync(0xffffffffu, m, off));
    if ((t & 31) == 0) smax[t >> 5] = m;
    __syncthreads();
    float mm = fmaxf(fmaxf(smax[0], smax[1]), 1e-20f);
    float inv = 127.0f / mm;
    #pragma unroll
    for (int j = 0; j < 9; j++)
        g_wq[co * KTOT + j * 64 + t] = q8(vals[j], inv);   // k' = khw*64 + ci
    if (t == 0) g_wsc[co] = (mm / 127.0f) * (XSCALE / 127.0f);
    out[t * COUT + co] = 0.0f;   // zero out[b=t][co], t = 0..63
}

// ---------------- main int8 implicit-GEMM kernel ----------------
// CTA tile: M128 (one oh row) x N128; 4 warps, warp tile 64x64.
// A smem [m][k] s8 (64B rows), B smem [n][k] s8; non-trans ldmatrix both.
// K=64 stages; STG=4 ring; 2 CTAs/SM; IMMA m16n8k32 s8->s32.

#define PA 80       // A smem row pitch bytes (conflict-free ldsm, stride 20 banks)
#define PB 80       // B smem row pitch bytes
#define STG 4
#define ASTG (128 * PA)   // 10240
#define BSTG (128 * PB)   // 10240

__device__ __forceinline__ uint32_t smem_u32(const void* p) {
    return (uint32_t)__cvta_generic_to_shared(p);
}

__device__ __forceinline__ void cp16(uint32_t dst, const void* src) {
    asm volatile("cp.async.cg.shared.global [%0], [%1], 16;\n" :: "r"(dst), "l"(src));
}

__device__ __forceinline__ void ldsm4(uint32_t& r0, uint32_t& r1, uint32_t& r2,
                                      uint32_t& r3, uint32_t addr) {
    asm volatile("ldmatrix.sync.aligned.m8n8.x4.shared.b16 {%0,%1,%2,%3}, [%4];"
                 : "=r"(r0), "=r"(r1), "=r"(r2), "=r"(r3) : "r"(addr));
}

__device__ __forceinline__ void imma16832(int c[4],
                                          uint32_t a0, uint32_t a1, uint32_t a2, uint32_t a3,
                                          uint32_t b0, uint32_t b1) {
    asm volatile("mma.sync.aligned.m16n8k32.row.col.s32.s8.s8.s32 "
                 "{%0,%1,%2,%3}, {%4,%5,%6,%7}, {%8,%9}, {%0,%1,%2,%3};"
                 : "+r"(c[0]), "+r"(c[1]), "+r"(c[2]), "+r"(c[3])
                 : "r"(a0), "r"(a1), "r"(a2), "r"(a3), "r"(b0), "r"(b1));
}

__device__ __forceinline__ float gelu_tanh(float x) {
    float x3 = x * x * x;
    float u = 0.7978845608028654f * fmaf(0.044715f, x3, x);
    float t;
    asm("tanh.approx.f32 %0, %1;" : "=f"(t) : "f"(u));
    return 0.5f * x * (1.0f + t);
}

__global__ void __launch_bounds__(128, 2)
conv_gemm_kernel(const float* __restrict__ bias, float* __restrict__ out) {
    extern __shared__ char dsm[];
    const uint32_t Abase = smem_u32(dsm);
    const uint32_t Bbase = Abase + STG * ASTG;

    const int tid    = threadIdx.x;
    const int lane   = tid & 31;
    const int warp   = tid >> 5;     // 0..3
    const int warp_m = warp >> 1;    // 0..1 -> 64 m-rows each
    const int warp_n = warp & 1;     // 0..1 -> 64 n-cols each
    const int oh = blockIdx.x;       // one output row per CTA
    const int n0 = blockIdx.y * 128; // COUT half
    const int b  = blockIdx.z;

    // staging roles: row = 4 shots of (i*32 + tid>>2), 16B chunk = tid&3
    const int sr = tid >> 2, sc = tid & 3;

    const int8_t* xb = g_xq + ((size_t)b * H) * W * CIN;
    const int8_t* wsrc = g_wq + (size_t)(n0 + sr) * KTOT + sc * 16;
    const uint32_t a_sdst = Abase + (uint32_t)(sr * PA + sc * 16);
    const uint32_t b_sdst = Bbase + (uint32_t)(sr * PB + sc * 16);

    // --- pipeline issue: one stage = K64 = one (kh,kw), ci 0..63 ---
    auto issue = [&](int st) {
        const int slot = st & (STG - 1);
        const int kh = (st * 11) >> 5;     // floor(st/3), st in [0,9)
        const int kw = st - kh * 3;
        const int8_t* asrc = xb + ((size_t)(oh + kh) * W + kw + sr) * CIN + sc * 16;
        const uint32_t ad = a_sdst + slot * ASTG;
        const uint32_t bd = b_sdst + slot * BSTG;
        #pragma unroll
        for (int i = 0; i < 4; i++) {      // rows i*32 + sr
            cp16(ad + i * (32 * PA), asrc + (size_t)i * 32 * CIN);
            cp16(bd + i * (32 * PB), wsrc + (size_t)i * 32 * KTOT + st * 64);
        }
        asm volatile("cp.async.commit_group;" ::: "memory");
    };

    issue(0); issue(1); issue(2);

    int acc[4][8][4];
    #pragma unroll
    for (int a = 0; a < 4; a++)
        #pragma unroll
        for (int c = 0; c < 8; c++)
            #pragma unroll
            for (int d = 0; d < 4; d++) acc[a][c][d] = 0;

    // ldmatrix lane addressing (constant per lane)
    // A (non-trans, [m][k]): row = lane&15, k-chunk-half = lane>>4
    const uint32_t a_loff = (uint32_t)((warp_m * 64 + (lane & 15)) * PA + (lane >> 4) * 16);
    // B (non-trans, [n][k]): row = (lane&7) + ((lane&16)>>1), chunk-half = (lane>>3)&1
    const uint32_t b_loff = (uint32_t)((warp_n * 64 + (lane & 7) + ((lane & 16) >> 1)) * PB
                                       + ((lane >> 3) & 1) * 16);

    // double-buffered fragments
    uint32_t afr[2][4][4];
    uint32_t bfr[2][8][2];

    #pragma unroll
    for (int st = 0; st < NSTG; st++) {
        if (st <= NSTG - 3)      asm volatile("cp.async.wait_group 2;" ::: "memory");
        else if (st == NSTG - 2) asm volatile("cp.async.wait_group 1;" ::: "memory");
        else                     asm volatile("cp.async.wait_group 0;" ::: "memory");
        __syncthreads();

        const int slot = st & (STG - 1);
        const uint32_t a_base = Abase + slot * ASTG + a_loff;
        const uint32_t b_base = Bbase + slot * BSTG + b_loff;

        // slice-0 fragments FIRST (k bytes 0..31) ...
        #pragma unroll
        for (int mi = 0; mi < 4; mi++)
            ldsm4(afr[0][mi][0], afr[0][mi][1], afr[0][mi][2], afr[0][mi][3],
                  a_base + (uint32_t)(mi * 16 * PA));
        #pragma unroll
        for (int q = 0; q < 4; q++)
            ldsm4(bfr[0][2*q][0], bfr[0][2*q][1], bfr[0][2*q+1][0], bfr[0][2*q+1][1],
                  b_base + (uint32_t)(q * 16 * PB));
        // ... then the non-urgent cp.async for stage st+3 (slot (st+3)&3 != st&3)
        if (st + 3 < NSTG) issue(st + 3);

        // 2 k32 slices, pipelined: ldsm(sl+1) before imma(sl)
        #pragma unroll
        for (int sl = 0; sl < 2; sl++) {
            const int cur = sl & 1, nxt = cur ^ 1;
            if (sl < 1) {
                #pragma unroll
                for (int mi = 0; mi < 4; mi++)
                    ldsm4(afr[nxt][mi][0], afr[nxt][mi][1], afr[nxt][mi][2], afr[nxt][mi][3],
                          a_base + (uint32_t)(mi * 16 * PA + 32));
                #pragma unroll
                for (int q = 0; q < 4; q++)
                    ldsm4(bfr[nxt][2*q][0], bfr[nxt][2*q][1],
                          bfr[nxt][2*q+1][0], bfr[nxt][2*q+1][1],
                          b_base + (uint32_t)(q * 16 * PB + 32));
            }
            #pragma unroll
            for (int mi = 0; mi < 4; mi++)
                #pragma unroll
                for (int ni = 0; ni < 8; ni++)
                    imma16832(acc[mi][ni],
                              afr[cur][mi][0], afr[cur][mi][1],
                              afr[cur][mi][2], afr[cur][mi][3],
                              bfr[cur][ni][0], bfr[cur][ni][1]);
        }
    }

    // ---- epilogue: dequant + bias + GELU + row-mean partial reduction ----
    const int group = lane >> 2;
    const int tid4  = lane & 3;

    float bcol[16], scol[16];
    #pragma unroll
    for (int j = 0; j < 16; j++) {
        int ni = j >> 1, bs = j & 1;
        int n = n0 + warp_n * 64 + ni * 8 + tid4 * 2 + bs;
        bcol[j] = bias[n];
        scol[j] = g_wsc[n];
    }

    float csum[16];
    #pragma unroll
    for (int j = 0; j < 16; j++) csum[j] = 0.0f;

    #pragma unroll
    for (int mi = 0; mi < 4; mi++) {
        #pragma unroll
        for (int half = 0; half < 2; half++) {
            int ow = warp_m * 64 + mi * 16 + half * 8 + group;
            bool ok = (ow < OW);
            #pragma unroll
            for (int ni = 0; ni < 8; ni++) {
                #pragma unroll
                for (int bs = 0; bs < 2; bs++) {
                    if (ok) {
                        int j = ni * 2 + bs;
                        float y = (float)acc[mi][ni][half * 2 + bs] * scol[j] + bcol[j];
                        csum[j] += gelu_tanh(y);
                    }
                }
            }
        }
    }

    // reduce over the 8 lane-groups holding the same columns
    #pragma unroll
    for (int j = 0; j < 16; j++) {
        csum[j] += __shfl_xor_sync(0xffffffffu, csum[j], 16);
        csum[j] += __shfl_xor_sync(0xffffffffu, csum[j], 8);
        csum[j] += __shfl_xor_sync(0xffffffffu, csum[j], 4);
    }

    if (lane < 4) {
        const float inv = 1.0f / (float)MTOT;
        #pragma unroll
        for (int j = 0; j < 16; j++) {
            int ni = j >> 1, bs = j & 1;
            int n = n0 + warp_n * 64 + ni * 8 + tid4 * 2 + bs;
            atomicAdd(&out[b * COUT + n], csum[j] * inv);
        }
    }
}

// ---------------- launch ----------------

#define DSMEM_BYTES (STG * (ASTG + BSTG))   // 81920

extern "C" void kernel_launch(void* const* d_in, const int* in_sizes, int n_in,
                              void* d_out, int out_size) {
    const float* x    = (const float*)d_in[0];   // [64,64,128,128]
    const float* w    = (const float*)d_in[1];   // [256,64,3,3]
    const float* bias = (const float*)d_in[2];   // [256]
    float* out = (float*)d_out;                  // [64,256]

    cudaFuncSetAttribute(conv_gemm_kernel,
                         cudaFuncAttributeMaxDynamicSharedMemorySize, DSMEM_BYTES);

    // 1) x -> s8 NHWC (fixed 6-sigma scale)
    quant_x_kernel<<<dim3(H, BATCH), 256>>>(x);
    // 2) weights -> s8 per-channel-max, K-reordered [co][k']; zero output
    quant_w_kernel<<<COUT, 64>>>(w, out);
    // 3) fused int8 implicit-GEMM conv + dequant + bias + GELU + mean-pool
    dim3 grid(OH, 2, BATCH);    // (126, 2 n-halves, 64)
    conv_gemm_kernel<<<grid, 128, DSMEM_BYTES>>>(bias, out);
}

// round 15
// speedup vs baseline: 3.2026x; 3.2026x over previous
#include <cuda_runtime.h>
#include <cuda_bf16.h>
#include <cstdint>

// Problem constants
#define BATCH 64
#define CIN   64
#define H     128
#define W     128
#define COUT  256
#define OH    126
#define OW    126
#define MTOT  (OH*OW)     // 15876
#define KTOT  (CIN*9)     // 576
#define NSTG  9           // 9 stages of K=64 (one per (kh,kw))

// Scratch (__device__ globals: allocation-free; zero-initialized pad)
// x in NHWC bf16: g_xn[b][h][w][ci]; +256 elems pad for edge-row overreads
__device__ __align__(16) __nv_bfloat16 g_xn[(size_t)BATCH*H*W*CIN + 256];
// weights bf16, n-major K-reordered rows: g_wb2[co][k'], k' = (kh*3+kw)*64 + ci
__device__ __align__(16) __nv_bfloat16 g_wb2[COUT*KTOT];

// ---------------- prologue kernels ----------------

__global__ void cvt_nhwc_kernel(const float* __restrict__ x) {
    // one block per (h, b): transpose the [64c][128w] slice to [w][c] in bf16
    __shared__ __nv_bfloat16 tile[64 * 130];
    const int h = blockIdx.x, b = blockIdx.y, tid = threadIdx.x;
    #pragma unroll
    for (int i = 0; i < 32; i++) {
        int idx = tid + i * 256;           // 8192 elements
        int c = idx >> 7, w = idx & 127;
        tile[c * 130 + w] =
            __float2bfloat16(x[(((size_t)b * CIN + c) * H + h) * W + w]);
    }
    __syncthreads();
    __nv_bfloat16* dst = g_xn + (((size_t)b * H + h) * W) * CIN;
    #pragma unroll
    for (int i = 0; i < 32; i++) {
        int idx = tid + i * 256;
        int w = idx >> 6, c = idx & 63;
        dst[(size_t)w * CIN + c] = tile[c * 130 + w];
    }
}

// weights reorder (n-major rows) + output zero in one launch
__global__ void cvt_w_zero_kernel(const float* __restrict__ w, float* __restrict__ out) {
    const int co = blockIdx.x;     // 0..255
    const int t  = threadIdx.x;    // 0..63 (= ci)
    #pragma unroll
    for (int j = 0; j < 9; j++)    // k' = j*64 + ci
        g_wb2[co * KTOT + j * 64 + t] = __float2bfloat16(w[co * KTOT + t * 9 + j]);
    out[t * COUT + co] = 0.0f;     // zero out[b=t][co]
}

// ---------------- main implicit-GEMM kernel ----------------
// CTA tile: M128 (one oh row) x N128; 4 warps, warp tile 64x64.
// A smem [m][k] bf16 128B rows, B smem [n][k] bf16 128B rows, both with
// XOR-swizzled 16B chunks (chunk ^ (row&7)). Non-trans ldmatrix for both.
// K=64 stages (one (kh,kw) each); STG=3 ring; 2 CTAs/SM (196KB total smem).

#define STG 3
#define ASTG 16384     // 128 rows x 128 B
#define BSTG 16384

__device__ __forceinline__ uint32_t smem_u32(const void* p) {
    return (uint32_t)__cvta_generic_to_shared(p);
}

__device__ __forceinline__ void cp16(uint32_t dst, const void* src) {
    asm volatile("cp.async.cg.shared.global [%0], [%1], 16;\n" :: "r"(dst), "l"(src));
}

__device__ __forceinline__ void ldsm4(uint32_t& r0, uint32_t& r1, uint32_t& r2,
                                      uint32_t& r3, uint32_t addr) {
    asm volatile("ldmatrix.sync.aligned.m8n8.x4.shared.b16 {%0,%1,%2,%3}, [%4];"
                 : "=r"(r0), "=r"(r1), "=r"(r2), "=r"(r3) : "r"(addr));
}

__device__ __forceinline__ void mma16816(float c[4],
                                         uint32_t a0, uint32_t a1, uint32_t a2, uint32_t a3,
                                         uint32_t b0, uint32_t b1) {
    asm volatile("mma.sync.aligned.m16n8k16.row.col.f32.bf16.bf16.f32 "
                 "{%0,%1,%2,%3}, {%4,%5,%6,%7}, {%8,%9}, {%0,%1,%2,%3};"
                 : "+f"(c[0]), "+f"(c[1]), "+f"(c[2]), "+f"(c[3])
                 : "r"(a0), "r"(a1), "r"(a2), "r"(a3), "r"(b0), "r"(b1));
}

__device__ __forceinline__ float gelu_tanh(float x) {
    float x3 = x * x * x;
    float u = 0.7978845608028654f * fmaf(0.044715f, x3, x);
    float t;
    asm("tanh.approx.f32 %0, %1;" : "=f"(t) : "f"(u));
    return 0.5f * x * (1.0f + t);
}

__global__ void __launch_bounds__(128, 2)
conv_gemm_kernel(const float* __restrict__ bias, float* __restrict__ out) {
    extern __shared__ char dsm[];
    const uint32_t Abase = smem_u32(dsm);
    const uint32_t Bbase = Abase + STG * ASTG;

    const int tid    = threadIdx.x;
    const int lane   = tid & 31;
    const int warp   = tid >> 5;     // 0..3
    const int warp_m = warp >> 1;    // 0..1 -> 64 m-rows each
    const int warp_n = warp & 1;     // 0..1 -> 64 n-cols each
    const int oh = blockIdx.x;       // one output row per CTA
    const int n0 = blockIdx.y * 128; // COUT half
    const int b  = blockIdx.z;

    // staging roles: warp writes 4 full 128B rows per instr (4-phase floor)
    const int srow = tid >> 3;       // 0..15 (rows srow + 16i)
    const int sj   = tid & 7;        // 16B chunk within row
    const uint32_t sdoff = (uint32_t)(srow * 128 + ((sj ^ (srow & 7)) << 4));

    const __nv_bfloat16* xb = g_xn + (size_t)b * H * W * CIN;
    const __nv_bfloat16* wb = g_wb2 + (size_t)n0 * KTOT;

    // --- pipeline issue: one stage = K64 = one (kh,kw), ci 0..63 ---
    auto issue = [&](int st) {
        const int slot = st % STG;
        const int kh = (st * 11) >> 5;     // floor(st/3), st in [0,9)
        const int kw = st - kh * 3;
        const __nv_bfloat16* asrc =
            xb + ((size_t)(oh + kh) * W + srow + kw) * CIN + sj * 8;
        const __nv_bfloat16* bsrc = wb + (size_t)srow * KTOT + st * 64 + sj * 8;
        const uint32_t ad = Abase + slot * ASTG + sdoff;
        const uint32_t bd = Bbase + slot * BSTG + sdoff;
        #pragma unroll
        for (int i = 0; i < 8; i++) {      // rows srow + 16i  (swizzle invariant mod 8)
            cp16(ad + i * 2048, asrc + (size_t)i * 16 * CIN);
            cp16(bd + i * 2048, bsrc + (size_t)i * 16 * KTOT);
        }
        asm volatile("cp.async.commit_group;" ::: "memory");
    };

    issue(0); issue(1);

    float acc[4][8][4];
    #pragma unroll
    for (int a = 0; a < 4; a++)
        #pragma unroll
        for (int c = 0; c < 8; c++)
            #pragma unroll
            for (int d = 0; d < 4; d++) acc[a][c][d] = 0.0f;

    // ldmatrix lane addressing (constant per lane), XOR swizzle = lane&7
    const uint32_t swz    = (uint32_t)(lane & 7);
    const uint32_t a_lrow = (uint32_t)((warp_m * 64 + (lane & 15)) * 128);
    const uint32_t a_kh   = (uint32_t)(lane >> 4);                 // 0/1
    const uint32_t b_lrow = (uint32_t)((warp_n * 64 + (lane & 7) + ((lane & 16) >> 1)) * 128);
    const uint32_t b_kh   = (uint32_t)((lane >> 3) & 1);           // 0/1

    // double-buffered fragments (2 x 32 regs)
    uint32_t afr[2][4][4];
    uint32_t bfr[2][8][2];

    #pragma unroll
    for (int st = 0; st < NSTG; st++) {
        if (st < NSTG - 2) asm volatile("cp.async.wait_group 1;" ::: "memory");
        else               asm volatile("cp.async.wait_group 0;" ::: "memory");
        __syncthreads();

        const int slot = st % STG;
        const uint32_t a_base = Abase + slot * ASTG + a_lrow;
        const uint32_t b_base = Bbase + slot * BSTG + b_lrow;

        // slice-0 fragments FIRST (tensor pipe restarts ASAP) ...
        {
            const uint32_t ach = ((0 + a_kh) ^ swz) << 4;
            const uint32_t bch = ((0 + b_kh) ^ swz) << 4;
            #pragma unroll
            for (int mi = 0; mi < 4; mi++)
                ldsm4(afr[0][mi][0], afr[0][mi][1], afr[0][mi][2], afr[0][mi][3],
                      a_base + (uint32_t)(mi * 2048) + ach);
            #pragma unroll
            for (int q = 0; q < 4; q++)
                ldsm4(bfr[0][2*q][0], bfr[0][2*q][1], bfr[0][2*q+1][0], bfr[0][2*q+1][1],
                      b_base + (uint32_t)(q * 2048) + bch);
        }
        // ... then the non-urgent cp.async for stage st+2 (slot (st+2)%3 != st%3)
        if (st + 2 < NSTG) issue(st + 2);

        // pipelined slices: ldsm(sl+1) before mma(sl)
        #pragma unroll
        for (int sl = 0; sl < 4; sl++) {
            const int cur = sl & 1, nxt = cur ^ 1;
            if (sl < 3) {
                const uint32_t ach = (((uint32_t)(sl + 1) * 2 + a_kh) ^ swz) << 4;
                const uint32_t bch = (((uint32_t)(sl + 1) * 2 + b_kh) ^ swz) << 4;
                #pragma unroll
                for (int mi = 0; mi < 4; mi++)
                    ldsm4(afr[nxt][mi][0], afr[nxt][mi][1], afr[nxt][mi][2], afr[nxt][mi][3],
                          a_base + (uint32_t)(mi * 2048) + ach);
                #pragma unroll
                for (int q = 0; q < 4; q++)
                    ldsm4(bfr[nxt][2*q][0], bfr[nxt][2*q][1],
                          bfr[nxt][2*q+1][0], bfr[nxt][2*q+1][1],
                          b_base + (uint32_t)(q * 2048) + bch);
            }
            #pragma unroll
            for (int mi = 0; mi < 4; mi++)
                #pragma unroll
                for (int ni = 0; ni < 8; ni++)
                    mma16816(acc[mi][ni],
                             afr[cur][mi][0], afr[cur][mi][1],
                             afr[cur][mi][2], afr[cur][mi][3],
                             bfr[cur][ni][0], bfr[cur][ni][1]);
        }
    }

    // ---- epilogue: bias + GELU + row-mean partial reduction ----
    const int group = lane >> 2;
    const int tid4  = lane & 3;

    float bcol[16];
    #pragma unroll
    for (int j = 0; j < 16; j++) {
        int ni = j >> 1, bs = j & 1;
        bcol[j] = bias[n0 + warp_n * 64 + ni * 8 + tid4 * 2 + bs];
    }

    float csum[16];
    #pragma unroll
    for (int j = 0; j < 16; j++) csum[j] = 0.0f;

    #pragma unroll
    for (int mi = 0; mi < 4; mi++) {
        #pragma unroll
        for (int half = 0; half < 2; half++) {
            int ow = warp_m * 64 + mi * 16 + half * 8 + group;
            bool ok = (ow < OW);
            #pragma unroll
            for (int ni = 0; ni < 8; ni++) {
                #pragma unroll
                for (int bs = 0; bs < 2; bs++) {
                    if (ok) {
                        float y = acc[mi][ni][half * 2 + bs] + bcol[ni * 2 + bs];
                        csum[ni * 2 + bs] += gelu_tanh(y);
                    }
                }
            }
        }
    }

    // reduce over the 8 lane-groups holding the same columns
    #pragma unroll
    for (int j = 0; j < 16; j++) {
        csum[j] += __shfl_xor_sync(0xffffffffu, csum[j], 16);
        csum[j] += __shfl_xor_sync(0xffffffffu, csum[j], 8);
        csum[j] += __shfl_xor_sync(0xffffffffu, csum[j], 4);
    }

    if (lane < 4) {
        const float inv = 1.0f / (float)MTOT;
        #pragma unroll
        for (int j = 0; j < 16; j++) {
            int ni = j >> 1, bs = j & 1;
            int n = n0 + warp_n * 64 + ni * 8 + tid4 * 2 + bs;
            atomicAdd(&out[b * COUT + n], csum[j] * inv);
        }
    }
}

// ---------------- launch ----------------

#define DSMEM_BYTES (STG * (ASTG + BSTG))   // 98304 -> 2 CTAs/SM (196KB < R12's 208KB)

extern "C" void kernel_launch(void* const* d_in, const int* in_sizes, int n_in,
                              void* d_out, int out_size) {
    const float* x    = (const float*)d_in[0];   // [64,64,128,128]
    const float* w    = (const float*)d_in[1];   // [256,64,3,3]
    const float* bias = (const float*)d_in[2];   // [256]
    float* out = (float*)d_out;                  // [64,256]

    cudaFuncSetAttribute(conv_gemm_kernel,
                         cudaFuncAttributeMaxDynamicSharedMemorySize, DSMEM_BYTES);

    // 1) x -> NHWC bf16 single copy (kw shift is now a row offset)
    cvt_nhwc_kernel<<<dim3(H, BATCH), 256>>>(x);
    // 2) weights -> bf16 n-major rows [co][k']; zero output accumulator
    cvt_w_zero_kernel<<<COUT, 64>>>(w, out);
    // 3) fused implicit-GEMM conv + bias + GELU + mean-pool
    dim3 grid(OH, 2, BATCH);    // (126, 2 n-halves, 64)
    conv_gemm_kernel<<<grid, 128, DSMEM_BYTES>>>(bias, out);
}